// round 7
// baseline (speedup 1.0000x reference)
#include <cuda_runtime.h>
#include <cuda_bf16.h>
#include <stdint.h>
#include <math.h>

#define B_ 8
#define N_ 2048
#define M_ 256
#define Q_ 16384
#define D_ 32
#define K_ 16
#define H_ 64
#define LAM_ 5.0f
#define CG_ITERS_ 20
#define RADIUS_ 0.005859375f   // 1.5/256

// out layout: s_pred [B,Q] | c0 [B,M,D] | c [B,M,D]
#define C0_OFF 131072
#define C_OFF  196608

__device__ float g_gw[B_][D_];

// ---------------- helpers ----------------
__device__ __forceinline__ uint32_t smem_u32(const void* p) {
    return (uint32_t)__cvta_generic_to_shared(p);
}
__device__ __forceinline__ uint32_t mapa_rank(uint32_t addr, uint32_t rank) {
    uint32_t r;
    asm("mapa.shared::cluster.u32 %0, %1, %2;" : "=r"(r) : "r"(addr), "r"(rank));
    return r;
}
__device__ __forceinline__ void st_cluster(uint32_t addr, float v) {
    asm volatile("st.shared::cluster.f32 [%0], %1;" :: "r"(addr), "f"(v));
}
__device__ __forceinline__ void cluster_arrive_() {
    asm volatile("barrier.cluster.arrive.aligned;" ::: "memory");
}
__device__ __forceinline__ void cluster_wait_() {
    asm volatile("barrier.cluster.wait.aligned;" ::: "memory");
}

// ---------------- kernel 1: global gate ----------------
__global__ void __launch_bounds__(1024) g_kernel(
    const float* __restrict__ xs, const float* __restrict__ us,
    const float* __restrict__ Wg1, const float* __restrict__ bg1,
    const float* __restrict__ Wg2, const float* __restrict__ bg2)
{
    int b = blockIdx.x, t = threadIdx.x;
    int h = t & 63, grp = t >> 6;
    float w0 = Wg1[h], w1 = Wg1[H_ + h], bb = bg1[h];
    float acc = 0.f;
    const float* xb = xs + b * N_;
    const float* ub = us + b * N_;
    int nbeg = grp * 128, nend = nbeg + 128;
#pragma unroll 4
    for (int n = nbeg; n < nend; n++)
        acc += fmaxf(fmaf(xb[n], w0, fmaf(ub[n], w1, bb)), 0.f);
    __shared__ float red[16][H_];
    __shared__ float gh[H_];
    red[grp][h] = acc;
    __syncthreads();
    if (t < H_) {
        float s = 0.f;
#pragma unroll
        for (int g = 0; g < 16; g++) s += red[g][t];
        gh[t] = s * (1.0f / (float)N_);
    }
    __syncthreads();
    if (t < D_) {
        float v = bg2[t];
#pragma unroll 8
        for (int hh = 0; hh < H_; hh++) v = fmaf(gh[hh], Wg2[hh * D_ + t], v);
        g_gw[b][t] = v;
    }
}

// ---------------- kernel 2: encode ----------------
__global__ void __launch_bounds__(256) encode_kernel(
    const float* __restrict__ xs, const float* __restrict__ us,
    const float* __restrict__ centers,
    const float* __restrict__ W1, const float* __restrict__ b1,
    const float* __restrict__ W2, const float* __restrict__ b2,
    const float* __restrict__ W3, const float* __restrict__ b3,
    const int* __restrict__ idx, float* __restrict__ out)
{
    __shared__ float W2s[H_ * H_];
    __shared__ __align__(16) float h1T[4][H_ * K_];
    __shared__ float rel_s[4][K_], u_s[4][K_];
    __shared__ float hb[4][H_];

    int u = threadIdx.x >> 6;
    int lt = threadIdx.x & 63;
    int bm = blockIdx.x * 4 + u;
    int b = bm >> 8, m = bm & 255;

    {
        const float4* src = (const float4*)W2;
        float4* dst = (float4*)W2s;
#pragma unroll
        for (int i = 0; i < 4; i++) dst[threadIdx.x + i * 256] = src[threadIdx.x + i * 256];
    }
    if (lt < K_) {
        int sj = idx[m * K_ + lt];
        rel_s[u][lt] = (xs[b * N_ + sj] - centers[m]) / RADIUS_;
        u_s[u][lt] = us[b * N_ + sj];
    }
    __syncthreads();

    {
        float w10 = W1[lt], w11 = W1[H_ + lt], bb1 = b1[lt];
#pragma unroll
        for (int k = 0; k < K_; k++)
            h1T[u][lt * K_ + k] = fmaxf(fmaf(rel_s[u][k], w10, fmaf(u_s[u][k], w11, bb1)), 0.f);
    }
    __syncthreads();

    {
        float acc[K_];
        float bb2 = b2[lt];
#pragma unroll
        for (int k = 0; k < K_; k++) acc[k] = bb2;
        for (int jj = 0; jj < H_; jj++) {
            float wv = W2s[jj * H_ + lt];
            const float4* hp = (const float4*)(h1T[u] + jj * K_);
#pragma unroll
            for (int kk = 0; kk < 4; kk++) {
                float4 h4 = hp[kk];
                acc[kk * 4 + 0] = fmaf(h4.x, wv, acc[kk * 4 + 0]);
                acc[kk * 4 + 1] = fmaf(h4.y, wv, acc[kk * 4 + 1]);
                acc[kk * 4 + 2] = fmaf(h4.z, wv, acc[kk * 4 + 2]);
                acc[kk * 4 + 3] = fmaf(h4.w, wv, acc[kk * 4 + 3]);
            }
        }
        float accm = 0.f;
#pragma unroll
        for (int k = 0; k < K_; k++) accm += fmaxf(acc[k], 0.f);
        hb[u][lt] = accm * (1.0f / (float)K_);
    }
    __syncthreads();

    if (lt < D_) {
        float v = b3[lt];
#pragma unroll 8
        for (int h = 0; h < H_; h++) v = fmaf(hb[u][h], W3[h * D_ + lt], v);
        out[C0_OFF + bm * D_ + lt] = v + g_gw[b][lt];
    }
}

// ---------------- kernel 3: sheaf CG — 2 batches per 8-CTA cluster ----------------
#define NT_CG 544
#define PB_ 7824
#define OFF_R   0
#define OFF_W   1088
#define OFF_P   2112
#define OFF_S   3136
#define OFF_X   4160
#define OFF_RE  5184
#define OFF_GSE 5712
#define OFF_GDE 6768
#define OFF_SH   (2*PB_)
#define OFF_RIN  (OFF_SH+128)
#define OFF_WB   (OFF_RIN+128)
#define OFF_PART (OFF_WB+256)
#define OFF_WRED (OFF_PART+64)
#define CG_SMEM_FLOATS (OFF_WRED+68)
#define CG_SMEM_BYTES (CG_SMEM_FLOATS*4)

// same edge, two batches interleaved (shared R registers)
__device__ __forceinline__ void edge_r_pair(const float (&Rs)[16], const float (&Rd)[16],
    const float* __restrict__ ra, const float* __restrict__ rb, int row,
    float* __restrict__ re0, float* __restrict__ re1, int lane, int riMap)
{
    float a0 = ra[row * 32 + lane], c0 = ra[row * 32 + 32 + lane];
    float a1 = rb[row * 32 + lane], c1 = rb[row * 32 + 32 + lane];
    float v0[16], v1[16];
#pragma unroll
    for (int ri = 0; ri < 16; ri++) {
        v0[ri] = Rs[ri] * a0; v0[ri] = fmaf(-Rd[ri], c0, v0[ri]);
        v1[ri] = Rs[ri] * a1; v1[ri] = fmaf(-Rd[ri], c1, v1[ri]);
    }
    {
        const bool bb = (lane & 16) != 0;
#pragma unroll
        for (int t = 0; t < 8; t++) {
            float s0 = bb ? v0[t] : v0[t + 8], k0 = bb ? v0[t + 8] : v0[t];
            v0[t] = k0 + __shfl_xor_sync(0xffffffffu, s0, 16);
            float s1 = bb ? v1[t] : v1[t + 8], k1 = bb ? v1[t + 8] : v1[t];
            v1[t] = k1 + __shfl_xor_sync(0xffffffffu, s1, 16);
        }
    }
    {
        const bool bb = (lane & 8) != 0;
#pragma unroll
        for (int t = 0; t < 4; t++) {
            float s0 = bb ? v0[t] : v0[t + 4], k0 = bb ? v0[t + 4] : v0[t];
            v0[t] = k0 + __shfl_xor_sync(0xffffffffu, s0, 8);
            float s1 = bb ? v1[t] : v1[t + 4], k1 = bb ? v1[t + 4] : v1[t];
            v1[t] = k1 + __shfl_xor_sync(0xffffffffu, s1, 8);
        }
    }
    {
        const bool bb = (lane & 4) != 0;
#pragma unroll
        for (int t = 0; t < 2; t++) {
            float s0 = bb ? v0[t] : v0[t + 2], k0 = bb ? v0[t + 2] : v0[t];
            v0[t] = k0 + __shfl_xor_sync(0xffffffffu, s0, 4);
            float s1 = bb ? v1[t] : v1[t + 2], k1 = bb ? v1[t + 2] : v1[t];
            v1[t] = k1 + __shfl_xor_sync(0xffffffffu, s1, 4);
        }
    }
    {
        const bool bb = (lane & 2) != 0;
        float s0 = bb ? v0[0] : v0[1], k0 = bb ? v0[1] : v0[0];
        v0[0] = k0 + __shfl_xor_sync(0xffffffffu, s0, 2);
        float s1 = bb ? v1[0] : v1[1], k1 = bb ? v1[1] : v1[0];
        v1[0] = k1 + __shfl_xor_sync(0xffffffffu, s1, 2);
    }
    v0[0] += __shfl_xor_sync(0xffffffffu, v0[0], 1);
    v1[0] += __shfl_xor_sync(0xffffffffu, v1[0], 1);
    if ((lane & 1) == 0) { re0[riMap] = v0[0]; re1[riMap] = v1[0]; }
}

__device__ __forceinline__ void edge_g_pair(const float (&Rs)[16], const float (&Rd)[16],
    const float* __restrict__ re0, const float* __restrict__ re1,
    float* __restrict__ gs0, float* __restrict__ gd0,
    float* __restrict__ gs1, float* __restrict__ gd1, int lane)
{
    float a0 = 0.f, b0 = 0.f, a1 = 0.f, b1 = 0.f;
#pragma unroll
    for (int ri = 0; ri < 16; ri++) {
        float r0v = re0[ri], r1v = re1[ri];
        a0 = fmaf(Rs[ri], r0v, a0); b0 = fmaf(Rd[ri], r0v, b0);
        a1 = fmaf(Rs[ri], r1v, a1); b1 = fmaf(Rd[ri], r1v, b1);
    }
    gs0[lane] = a0; gd0[lane] = b0; gs1[lane] = a1; gd1[lane] = b1;
}

__global__ void __cluster_dims__(8, 1, 1) __launch_bounds__(NT_CG, 1) cg_kernel(
    const float* __restrict__ Rsrc, const float* __restrict__ Rdst,
    float* __restrict__ out)
{
    extern __shared__ float sm[];
    const int cl = blockIdx.x >> 3, j = blockIdx.x & 7;
    const int b0 = 2 * cl, b1 = 2 * cl + 1;
    const int tid = threadIdx.x, w = tid >> 5, lane = tid & 31;
    const int n0 = j * 32;
    const int eA = j ? (n0 - 1) : 0;
    const int nE = (j == 0 || j == 7) ? 32 : 33;
    const int riMap = ((lane >> 4) & 1) * 8 + ((lane >> 3) & 1) * 4 +
                      ((lane >> 2) & 1) * 2 + ((lane >> 1) & 1);
    const int el0 = 2 * w, el1 = 2 * w + 1;
    const bool h0 = el0 < nE, h1 = el1 < nE;
    const int row0 = eA + el0 - n0 + 1, row1 = row0 + 1;

    float* rA = sm + OFF_R;          float* rB = sm + PB_ + OFF_R;
    float* wA = sm + OFF_W;          float* wB = sm + PB_ + OFF_W;
    float* pA = sm + OFF_P;          float* pB = sm + PB_ + OFF_P;
    float* sA = sm + OFF_S;          float* sB = sm + PB_ + OFF_S;
    float* xA = sm + OFF_X;          float* xB = sm + PB_ + OFF_X;
    float* reA = sm + OFF_RE;        float* reB = sm + PB_ + OFF_RE;
    float* gseA = sm + OFF_GSE;      float* gseB = sm + PB_ + OFF_GSE;
    float* gdeA = sm + OFF_GDE;      float* gdeB = sm + PB_ + OFF_GDE;
    float* sh   = sm + OFF_SH;       // [bi*64 + side*32 + d]
    float* rin  = sm + OFF_RIN;      // [bi*64 + side*32 + d]
    float* wbb  = sm + OFF_WB;       // [buf*128 + bi*64 + side*32 + d]
    float* part = sm + OFF_PART;     // [buf*32 + rank*4 + bi*2 + v]
    float* wred = sm + OFF_WRED;     // [warp*4 + (bi*2+v)]

    float Rs0[16], Rd0[16], Rs1[16], Rd1[16];
    if (h0) {
        const float* a = Rsrc + (size_t)(eA + el0) * 512 + lane;
        const float* d = Rdst + (size_t)(eA + el0) * 512 + lane;
#pragma unroll
        for (int ri = 0; ri < 16; ri++) { Rs0[ri] = a[ri * 32]; Rd0[ri] = d[ri * 32]; }
    }
    if (h1) {
        const float* a = Rsrc + (size_t)(eA + el1) * 512 + lane;
        const float* d = Rdst + (size_t)(eA + el1) * 512 + lane;
#pragma unroll
        for (int ri = 0; ri < 16; ri++) { Rs1[ri] = a[ri * 32]; Rd1[ri] = d[ri * 32]; }
    }

    // apply for both batches; fused combine + dot partials (lg=r.r, ld=r.w)
    auto apply2 = [&](float& lg0, float& ld0, float& lg1, float& ld1) {
        if (h0) edge_r_pair(Rs0, Rd0, rA, rB, row0, reA + el0 * 16, reB + el0 * 16, lane, riMap);
        if (h1) edge_r_pair(Rs1, Rd1, rA, rB, row1, reA + el1 * 16, reB + el1 * 16, lane, riMap);
        __syncwarp();
        if (h0) edge_g_pair(Rs0, Rd0, reA + el0 * 16, reB + el0 * 16,
                            gseA + el0 * 32, gdeA + el0 * 32, gseB + el0 * 32, gdeB + el0 * 32, lane);
        if (h1) edge_g_pair(Rs1, Rd1, reA + el1 * 16, reB + el1 * 16,
                            gseA + el1 * 32, gdeA + el1 * 32, gseB + el1 * 32, gdeB + el1 * 32, lane);
        __syncthreads();
        for (int i = tid; i < 1024; i += NT_CG) {
            int n = n0 + (i >> 5), d = i & 31;
            int ie = (n - eA) * 32 + d, ie2 = (n - 1 - eA) * 32 + d;
            float accA = 0.f, accB = 0.f;
            if (n <= 254) { accA = gseA[ie]; accB = gseB[ie]; }
            if (n >= 1)   { accA -= gdeA[ie2]; accB -= gdeB[ie2]; }
            float rrA = rA[i + 32], rrB = rB[i + 32];
            float wwA = fmaf(LAM_, accA, rrA), wwB = fmaf(LAM_, accB, rrB);
            wA[i] = wwA; wB[i] = wwB;
            lg0 = fmaf(rrA, rrA, lg0); ld0 = fmaf(rrA, wwA, ld0);
            lg1 = fmaf(rrB, rrB, lg1); ld1 = fmaf(rrB, wwB, ld1);
        }
    };
    // reduce 4 partials across block into wred, sync, then threads 0..15 export
    auto reduce_export = [&](float lg0, float ld0, float lg1, float ld1, int buf) {
#pragma unroll
        for (int o = 16; o; o >>= 1) {
            lg0 += __shfl_xor_sync(0xffffffffu, lg0, o);
            ld0 += __shfl_xor_sync(0xffffffffu, ld0, o);
            lg1 += __shfl_xor_sync(0xffffffffu, lg1, o);
            ld1 += __shfl_xor_sync(0xffffffffu, ld1, o);
        }
        if (lane == 0) { wred[w * 4] = lg0; wred[w * 4 + 1] = ld0; wred[w * 4 + 2] = lg1; wred[w * 4 + 3] = ld1; }
        __syncthreads();
        if (tid < 16) {
            int bi = tid >> 3, k = tid & 7;
            float sg = 0.f, sd = 0.f;
#pragma unroll
            for (int w2 = 0; w2 < 17; w2++) { sg += wred[w2 * 4 + bi * 2]; sd += wred[w2 * 4 + bi * 2 + 1]; }
            st_cluster(mapa_rank(smem_u32(&part[buf * 32 + j * 4 + bi * 2 + 0]), (uint32_t)k), sg);
            st_cluster(mapa_rank(smem_u32(&part[buf * 32 + j * 4 + bi * 2 + 1]), (uint32_t)k), sd);
        }
    };
    auto whalo_send = [&](int buf) {
        if (tid >= 64 && tid < 192) {
            int z = tid - 64, bi = z >> 6, s2 = (z >> 5) & 1, d = z & 31;
            const float* wp = bi ? wB : wA;
            if (s2 == 0) { if (j > 0) st_cluster(mapa_rank(smem_u32(&wbb[buf * 128 + bi * 64 + 32 + d]), j - 1), wp[d]); }
            else         { if (j < 7) st_cluster(mapa_rank(smem_u32(&wbb[buf * 128 + bi * 64 + d]), j + 1), wp[31 * 32 + d]); }
        }
    };

    // ---- prolog ----
    const float* c0A = out + C0_OFF + b0 * (M_ * D_);
    const float* c0B = out + C0_OFF + b1 * (M_ * D_);
    for (int i = tid; i < 34 * 32; i += NT_CG) {
        int node = n0 - 1 + (i >> 5);
        bool ok = (node >= 0 && node < M_);
        int gi = node * 32 + (i & 31);
        rA[i] = ok ? c0A[gi] : 0.f;
        rB[i] = ok ? c0B[gi] : 0.f;
    }
    __syncthreads();
    for (int i = tid; i < 1024; i += NT_CG) { xA[i] = rA[i + 32]; xB[i] = rB[i + 32]; }
    __syncthreads();

    { float z0 = 0, z1 = 0, z2 = 0, z3 = 0; apply2(z0, z1, z2, z3); }   // w = A c0
    __syncthreads();
    for (int i = tid; i < 1024; i += NT_CG) { rA[i + 32] = xA[i] - wA[i]; rB[i + 32] = xB[i] - wB[i]; }
    __syncthreads();

    // r0 halo exchange
    if (tid < 128) {
        int bi = tid >> 6, z = tid & 63, side = z >> 5, d = z & 31;
        const float* rr = bi ? rB : rA;
        if (side == 0) { if (j > 0) st_cluster(mapa_rank(smem_u32(&rin[bi * 64 + 32 + d]), j - 1), rr[32 + d]); }
        else           { if (j < 7) st_cluster(mapa_rank(smem_u32(&rin[bi * 64 + d]), j + 1), rr[32 * 32 + d]); }
    }
    cluster_arrive_(); cluster_wait_();
    if (tid < 128) {
        int bi = tid >> 6, z = tid & 63, side = z >> 5, d = z & 31;
        float* rr = bi ? rB : rA;
        if (side == 0) { if (j > 0) rr[d] = rin[bi * 64 + d]; }
        else           { if (j < 7) rr[33 * 32 + d] = rin[bi * 64 + 32 + d]; }
    }
    __syncthreads();

    float lg0 = 0, ld0 = 0, lg1 = 0, ld1 = 0;
    apply2(lg0, ld0, lg1, ld1);     // w = A r0, dots
    reduce_export(lg0, ld0, lg1, ld1, 0);
    whalo_send(0);
    cluster_arrive_(); cluster_wait_();

    float gam0 = 0, del0 = 0, gam1 = 0, del1 = 0;
#pragma unroll
    for (int k2 = 0; k2 < 8; k2++) {
        gam0 += part[k2 * 4];     del0 += part[k2 * 4 + 1];
        gam1 += part[k2 * 4 + 2]; del1 += part[k2 * 4 + 3];
    }
    float alpha0 = gam0 / (del0 + 1e-12f), alpha1 = gam1 / (del1 + 1e-12f);
    float gamp0 = gam0, gamp1 = gam1, alphap0 = alpha0, alphap1 = alpha1;

    // halo init: s_h = w_h; r_h -= alpha*s_h
    if (tid < 128) {
        int bi = tid >> 6, z = tid & 63, side = z >> 5, d = z & 31;
        bool act = side == 0 ? (j > 0) : (j < 7);
        if (act) {
            float* rr = bi ? rB : rA;
            float al = bi ? alpha1 : alpha0;
            float sv = wbb[bi * 64 + side * 32 + d];
            sh[bi * 64 + side * 32 + d] = sv;
            int ridx = side == 0 ? d : (33 * 32 + d);
            rr[ridx] = fmaf(-al, sv, rr[ridx]);
        }
    }
    for (int i = tid; i < 1024; i += NT_CG) {
        float r0v = rA[i + 32], w0v = wA[i];
        pA[i] = r0v; sA[i] = w0v; rA[i + 32] = fmaf(-alpha0, w0v, r0v);
        float r1v = rB[i + 32], w1v = wB[i];
        pB[i] = r1v; sB[i] = w1v; rB[i + 32] = fmaf(-alpha1, w1v, r1v);
    }
    __syncthreads();

    // ---- main loop ----
    for (int it = 1; it < CG_ITERS_; it++) {
        float g0 = 0, d0 = 0, g1 = 0, d1 = 0;
        apply2(g0, d0, g1, d1);
        const int buf = it & 1;
        reduce_export(g0, d0, g1, d1, buf);
        if (it < CG_ITERS_ - 1) whalo_send(buf);
        cluster_arrive_();
        // deferred x += alpha_prev * p (overlaps barrier wait)
        for (int i = tid; i < 1024; i += NT_CG) {
            xA[i] = fmaf(alphap0, pA[i], xA[i]);
            xB[i] = fmaf(alphap1, pB[i], xB[i]);
        }
        cluster_wait_();

        gam0 = 0; del0 = 0; gam1 = 0; del1 = 0;
#pragma unroll
        for (int k2 = 0; k2 < 8; k2++) {
            gam0 += part[buf * 32 + k2 * 4];     del0 += part[buf * 32 + k2 * 4 + 1];
            gam1 += part[buf * 32 + k2 * 4 + 2]; del1 += part[buf * 32 + k2 * 4 + 3];
        }
        float beta0 = gam0 / (gamp0 + 1e-12f);
        float beta1 = gam1 / (gamp1 + 1e-12f);
        alpha0 = gam0 / (del0 - beta0 * gam0 / alphap0 + 1e-12f);
        alpha1 = gam1 / (del1 - beta1 * gam1 / alphap1 + 1e-12f);
        gamp0 = gam0; gamp1 = gam1;

        if (it == CG_ITERS_ - 1) {
            float* ogA = out + C_OFF + b0 * (M_ * D_) + n0 * 32;
            float* ogB = out + C_OFF + b1 * (M_ * D_) + n0 * 32;
            for (int i = tid; i < 1024; i += NT_CG) {
                ogA[i] = fmaf(alpha0, fmaf(beta0, pA[i], rA[i + 32]), xA[i]);
                ogB[i] = fmaf(alpha1, fmaf(beta1, pB[i], rB[i + 32]), xB[i]);
            }
            return;
        }
        alphap0 = alpha0; alphap1 = alpha1;

        // halos: s_h = w_h + beta*s_h; r_h -= alpha*s_h
        if (tid < 128) {
            int bi = tid >> 6, z = tid & 63, side = z >> 5, d = z & 31;
            bool act = side == 0 ? (j > 0) : (j < 7);
            if (act) {
                float* rr = bi ? rB : rA;
                float al = bi ? alpha1 : alpha0, be = bi ? beta1 : beta0;
                int hidx = bi * 64 + side * 32 + d;
                float sv = fmaf(be, sh[hidx], wbb[buf * 128 + hidx]);
                sh[hidx] = sv;
                int ridx = side == 0 ? d : (33 * 32 + d);
                rr[ridx] = fmaf(-al, sv, rr[ridx]);
            }
        }
        // own: p = r + beta p; s = w + beta s; r -= alpha s (x deferred)
        for (int i = tid; i < 1024; i += NT_CG) {
            float r0v = rA[i + 32], w0v = wA[i];
            float p0v = fmaf(beta0, pA[i], r0v);
            float s0v = fmaf(beta0, sA[i], w0v);
            rA[i + 32] = fmaf(-alpha0, s0v, r0v); pA[i] = p0v; sA[i] = s0v;
            float r1v = rB[i + 32], w1v = wB[i];
            float p1v = fmaf(beta1, pB[i], r1v);
            float s1v = fmaf(beta1, sB[i], w1v);
            rB[i + 32] = fmaf(-alpha1, s1v, r1v); pB[i] = p1v; sB[i] = s1v;
        }
        __syncthreads();
    }
}

// ---------------- kernel 4: query eval (8 threads per q) ----------------
__global__ void __launch_bounds__(256) query_kernel(
    const float* __restrict__ phi_q, const float* __restrict__ out_c,
    float* __restrict__ out)
{
    __shared__ float4 c_s[512];   // [mm(8)][b(8)][d4(8)]
    int q0 = blockIdx.x * 32;
    int mbase = (int)floorf((q0 + 0.5f) * 0.015625f) - 2;
    if (mbase < 0) mbase = 0;
    if (mbase > M_ - 8) mbase = M_ - 8;

    const float4* cg4 = (const float4*)out_c;
    for (int i = threadIdx.x; i < 512; i += 256) {
        int mm = i >> 6, rem = i & 63;
        int bb2 = rem >> 3, d4 = rem & 7;
        c_s[i] = cg4[((size_t)bb2 * M_ + (mbase + mm)) * 8 + d4];
    }
    __syncthreads();

    int ql = threadIdx.x >> 3;             // 0..31
    int dh = (threadIdx.x >> 2) & 1;       // d half
    int bq = threadIdx.x & 3;              // batches {bq, bq+4}
    int q = q0 + ql;
    float v = (q + 0.5f) * 0.015625f;
    int mlo = (int)floorf(v) - 1;
    float sacc[2] = {0.f, 0.f};
    float wsum = 0.f;

#pragma unroll
    for (int cand = 0; cand < 3; cand++) {
        int m = mlo + cand;
        if (m < 0 || m > M_ - 1) continue;
        float t = (v - (m + 0.5f)) * (1.0f / 1.5f);
        float wr = 1.0f - fabsf(t);
        if (wr <= 0.f) continue;
        wsum += wr;
        const float4* ph = (const float4*)(phi_q + ((size_t)m * Q_ + q) * 32) + dh * 4;
        float4 p4[4];
#pragma unroll
        for (int i = 0; i < 4; i++) p4[i] = __ldg(ph + i);
        int ms = m - mbase;
#pragma unroll
        for (int bb2 = 0; bb2 < 2; bb2++) {
            int batch = bq + bb2 * 4;
            const float4* cc = &c_s[(ms << 6) + (batch << 3) + dh * 4];
            float dot = 0.f;
#pragma unroll
            for (int i = 0; i < 4; i++) {
                float4 c4 = cc[i];
                dot = fmaf(p4[i].x, c4.x, dot);
                dot = fmaf(p4[i].y, c4.y, dot);
                dot = fmaf(p4[i].z, c4.z, dot);
                dot = fmaf(p4[i].w, c4.w, dot);
            }
            sacc[bb2] = fmaf(wr, dot, sacc[bb2]);
        }
    }
#pragma unroll
    for (int bb2 = 0; bb2 < 2; bb2++)
        sacc[bb2] += __shfl_xor_sync(0xffffffffu, sacc[bb2], 4);
    if (dh == 0) {
        float inv = 1.0f / fmaxf(wsum, 1e-8f);
        out[(size_t)bq * Q_ + q] = sacc[0] * inv;
        out[(size_t)(bq + 4) * Q_ + q] = sacc[1] * inv;
    }
}

// ---------------- launch ----------------
extern "C" void kernel_launch(void* const* d_in, const int* in_sizes, int n_in,
                              void* d_out, int out_size) {
    const float* xs      = (const float*)d_in[0];
    const float* us      = (const float*)d_in[1];
    const float* phi_q   = (const float*)d_in[2];
    const float* centers = (const float*)d_in[4];
    const float* R_src   = (const float*)d_in[5];
    const float* R_dst   = (const float*)d_in[6];
    const float* W1      = (const float*)d_in[7];
    const float* b1      = (const float*)d_in[8];
    const float* W2      = (const float*)d_in[9];
    const float* b2      = (const float*)d_in[10];
    const float* W3      = (const float*)d_in[11];
    const float* b3      = (const float*)d_in[12];
    const float* Wg1     = (const float*)d_in[13];
    const float* bg1     = (const float*)d_in[14];
    const float* Wg2     = (const float*)d_in[15];
    const float* bg2     = (const float*)d_in[16];
    const int*   idx     = (const int*)d_in[17];
    float* out = (float*)d_out;

    cudaFuncSetAttribute(cg_kernel, cudaFuncAttributeMaxDynamicSharedMemorySize, CG_SMEM_BYTES);

    g_kernel<<<B_, 1024>>>(xs, us, Wg1, bg1, Wg2, bg2);
    encode_kernel<<<B_ * M_ / 4, 256>>>(xs, us, centers, W1, b1, W2, b2, W3, b3, idx, out);
    cg_kernel<<<(B_ / 2) * 8, NT_CG, CG_SMEM_BYTES>>>(R_src, R_dst, out);
    query_kernel<<<Q_ / 32, 256>>>(phi_q, out + C_OFF, out);
}

// round 9
// speedup vs baseline: 1.3933x; 1.3933x over previous
#include <cuda_runtime.h>
#include <cuda_bf16.h>
#include <stdint.h>
#include <math.h>

#define B_ 8
#define N_ 2048
#define M_ 256
#define Q_ 16384
#define D_ 32
#define K_ 16
#define H_ 64
#define LAM_ 5.0f
#define CG_ITERS_ 20
#define RADIUS_ 0.005859375f   // 1.5/256

// out layout: s_pred [B,Q] | c0 [B,M,D] | c [B,M,D]
#define C0_OFF 131072
#define C_OFF  196608

__device__ float g_gw[B_][D_];

// ---------------- helpers ----------------
__device__ __forceinline__ uint32_t smem_u32(const void* p) {
    return (uint32_t)__cvta_generic_to_shared(p);
}
__device__ __forceinline__ uint32_t mapa_rank(uint32_t addr, uint32_t rank) {
    uint32_t r;
    asm("mapa.shared::cluster.u32 %0, %1, %2;" : "=r"(r) : "r"(addr), "r"(rank));
    return r;
}
__device__ __forceinline__ void st_cluster(uint32_t addr, float v) {
    asm volatile("st.shared::cluster.f32 [%0], %1;" :: "r"(addr), "f"(v));
}
__device__ __forceinline__ void cluster_arrive_() {
    asm volatile("barrier.cluster.arrive.aligned;" ::: "memory");
}
__device__ __forceinline__ void cluster_wait_() {
    asm volatile("barrier.cluster.wait.aligned;" ::: "memory");
}

// ---------------- kernel 1: global gate ----------------
__global__ void __launch_bounds__(1024) g_kernel(
    const float* __restrict__ xs, const float* __restrict__ us,
    const float* __restrict__ Wg1, const float* __restrict__ bg1,
    const float* __restrict__ Wg2, const float* __restrict__ bg2)
{
    int b = blockIdx.x, t = threadIdx.x;
    int h = t & 63, grp = t >> 6;
    float w0 = Wg1[h], w1 = Wg1[H_ + h], bb = bg1[h];
    float acc = 0.f;
    const float* xb = xs + b * N_;
    const float* ub = us + b * N_;
    int nbeg = grp * 128, nend = nbeg + 128;
#pragma unroll 4
    for (int n = nbeg; n < nend; n++)
        acc += fmaxf(fmaf(xb[n], w0, fmaf(ub[n], w1, bb)), 0.f);
    __shared__ float red[16][H_];
    __shared__ float gh[H_];
    red[grp][h] = acc;
    __syncthreads();
    if (t < H_) {
        float s = 0.f;
#pragma unroll
        for (int g = 0; g < 16; g++) s += red[g][t];
        gh[t] = s * (1.0f / (float)N_);
    }
    __syncthreads();
    if (t < D_) {
        float v = bg2[t];
#pragma unroll 8
        for (int hh = 0; hh < H_; hh++) v = fmaf(gh[hh], Wg2[hh * D_ + t], v);
        g_gw[b][t] = v;
    }
}

// ---------------- kernel 2: encode ----------------
__global__ void __launch_bounds__(256) encode_kernel(
    const float* __restrict__ xs, const float* __restrict__ us,
    const float* __restrict__ centers,
    const float* __restrict__ W1, const float* __restrict__ b1,
    const float* __restrict__ W2, const float* __restrict__ b2,
    const float* __restrict__ W3, const float* __restrict__ b3,
    const int* __restrict__ idx, float* __restrict__ out)
{
    __shared__ float W2s[H_ * H_];
    __shared__ __align__(16) float h1T[4][H_ * K_];
    __shared__ float rel_s[4][K_], u_s[4][K_];
    __shared__ float hb[4][H_];

    int u = threadIdx.x >> 6;
    int lt = threadIdx.x & 63;
    int bm = blockIdx.x * 4 + u;
    int b = bm >> 8, m = bm & 255;

    {
        const float4* src = (const float4*)W2;
        float4* dst = (float4*)W2s;
#pragma unroll
        for (int i = 0; i < 4; i++) dst[threadIdx.x + i * 256] = src[threadIdx.x + i * 256];
    }
    if (lt < K_) {
        int sj = idx[m * K_ + lt];
        rel_s[u][lt] = (xs[b * N_ + sj] - centers[m]) / RADIUS_;
        u_s[u][lt] = us[b * N_ + sj];
    }
    __syncthreads();

    {
        float w10 = W1[lt], w11 = W1[H_ + lt], bb1 = b1[lt];
#pragma unroll
        for (int k = 0; k < K_; k++)
            h1T[u][lt * K_ + k] = fmaxf(fmaf(rel_s[u][k], w10, fmaf(u_s[u][k], w11, bb1)), 0.f);
    }
    __syncthreads();

    {
        float acc[K_];
        float bb2 = b2[lt];
#pragma unroll
        for (int k = 0; k < K_; k++) acc[k] = bb2;
        for (int jj = 0; jj < H_; jj++) {
            float wv = W2s[jj * H_ + lt];
            const float4* hp = (const float4*)(h1T[u] + jj * K_);
#pragma unroll
            for (int kk = 0; kk < 4; kk++) {
                float4 h4 = hp[kk];
                acc[kk * 4 + 0] = fmaf(h4.x, wv, acc[kk * 4 + 0]);
                acc[kk * 4 + 1] = fmaf(h4.y, wv, acc[kk * 4 + 1]);
                acc[kk * 4 + 2] = fmaf(h4.z, wv, acc[kk * 4 + 2]);
                acc[kk * 4 + 3] = fmaf(h4.w, wv, acc[kk * 4 + 3]);
            }
        }
        float accm = 0.f;
#pragma unroll
        for (int k = 0; k < K_; k++) accm += fmaxf(acc[k], 0.f);
        hb[u][lt] = accm * (1.0f / (float)K_);
    }
    __syncthreads();

    if (lt < D_) {
        float v = b3[lt];
#pragma unroll 8
        for (int h = 0; h < H_; h++) v = fmaf(hb[u][h], W3[h * D_ + lt], v);
        out[C0_OFF + bm * D_ + lt] = v + g_gw[b][lt];
    }
}

// ---------------- kernel 3: sheaf CG (pipelined, register R, fused dots) ----------------
#define NT_CG 544   // 17 warps

__device__ __forceinline__ void edge_r_fn(const float (&Rs)[16], const float (&Rd)[16],
    const float* __restrict__ r_s, int rowA, float* __restrict__ re, int lane, int riMap)
{
    float a = r_s[rowA * 32 + lane];
    float c = r_s[rowA * 32 + 32 + lane];
    float v[16];
#pragma unroll
    for (int ri = 0; ri < 16; ri++) { v[ri] = Rs[ri] * a; v[ri] = fmaf(-Rd[ri], c, v[ri]); }
    {
        const bool bb = (lane & 16) != 0;
#pragma unroll
        for (int t = 0; t < 8; t++) {
            float snd = bb ? v[t] : v[t + 8];
            float kp  = bb ? v[t + 8] : v[t];
            v[t] = kp + __shfl_xor_sync(0xffffffffu, snd, 16);
        }
    }
    {
        const bool bb = (lane & 8) != 0;
#pragma unroll
        for (int t = 0; t < 4; t++) {
            float snd = bb ? v[t] : v[t + 4];
            float kp  = bb ? v[t + 4] : v[t];
            v[t] = kp + __shfl_xor_sync(0xffffffffu, snd, 8);
        }
    }
    {
        const bool bb = (lane & 4) != 0;
#pragma unroll
        for (int t = 0; t < 2; t++) {
            float snd = bb ? v[t] : v[t + 2];
            float kp  = bb ? v[t + 2] : v[t];
            v[t] = kp + __shfl_xor_sync(0xffffffffu, snd, 4);
        }
    }
    {
        const bool bb = (lane & 2) != 0;
        float snd = bb ? v[0] : v[1];
        float kp  = bb ? v[1] : v[0];
        v[0] = kp + __shfl_xor_sync(0xffffffffu, snd, 2);
    }
    v[0] += __shfl_xor_sync(0xffffffffu, v[0], 1);
    if ((lane & 1) == 0) re[riMap] = v[0];
}

__device__ __forceinline__ void edge_g_fn(const float (&Rs)[16], const float (&Rd)[16],
    const float* __restrict__ re, float* __restrict__ gs_o, float* __restrict__ gd_o, int lane)
{
    float gs = 0.f, gd = 0.f;
#pragma unroll
    for (int ri = 0; ri < 16; ri++) {
        float rv = re[ri];
        gs = fmaf(Rs[ri], rv, gs);
        gd = fmaf(Rd[ri], rv, gd);
    }
    gs_o[lane] = gs;
    gd_o[lane] = gd;
}

__global__ void __cluster_dims__(8, 1, 1) __launch_bounds__(NT_CG, 1) cg_kernel(
    const float* __restrict__ Rsrc, const float* __restrict__ Rdst,
    float* __restrict__ out)
{
    __shared__ float r_s[34 * 32];          // rows 0/33 = halos
    __shared__ float w_s[1024];
    __shared__ float p_s[1024];
    __shared__ float s_s[1024];
    __shared__ float x_s[1024];
    __shared__ float sh_[2][32];
    __shared__ float redge[33 * 16];
    __shared__ float gse[33 * 32], gde[33 * 32];
    __shared__ float part_in[2][8][2];
    __shared__ float rin[2][32];
    __shared__ float wb[2][2][32];
    __shared__ float wred[17][2];

    const int b = blockIdx.x >> 3, j = blockIdx.x & 7;
    const int tid = threadIdx.x, w = tid >> 5, lane = tid & 31;
    const int n0 = j * 32;
    const int eA = j ? (n0 - 1) : 0;
    const int nE = (j == 0 || j == 7) ? 32 : 33;
    const int riMap = ((lane >> 4) & 1) * 8 + ((lane >> 3) & 1) * 4 +
                      ((lane >> 2) & 1) * 2 + ((lane >> 1) & 1);

    const int el0 = 2 * w, el1 = 2 * w + 1;
    const bool h0 = el0 < nE, h1 = el1 < nE;
    const int row0 = eA + el0 - n0 + 1;
    const int row1 = row0 + 1;

    float Rs0[16], Rd0[16], Rs1[16], Rd1[16];
    if (h0) {
        const float* a = Rsrc + (size_t)(eA + el0) * 512 + lane;
        const float* d = Rdst + (size_t)(eA + el0) * 512 + lane;
#pragma unroll
        for (int ri = 0; ri < 16; ri++) { Rs0[ri] = a[ri * 32]; Rd0[ri] = d[ri * 32]; }
    }
    if (h1) {
        const float* a = Rsrc + (size_t)(eA + el1) * 512 + lane;
        const float* d = Rdst + (size_t)(eA + el1) * 512 + lane;
#pragma unroll
        for (int ri = 0; ri < 16; ri++) { Rs1[ri] = a[ri * 32]; Rd1[ri] = d[ri * 32]; }
    }

    // apply + fused dots: w = (I + LAM L) r over own nodes; lg += r.r, ld += r.w
    auto apply_fused = [&](float& lg, float& ld) {
        if (h0) edge_r_fn(Rs0, Rd0, r_s, row0, &redge[el0 * 16], lane, riMap);
        if (h1) edge_r_fn(Rs1, Rd1, r_s, row1, &redge[el1 * 16], lane, riMap);
        __syncwarp();
        if (h0) edge_g_fn(Rs0, Rd0, &redge[el0 * 16], &gse[el0 * 32], &gde[el0 * 32], lane);
        if (h1) edge_g_fn(Rs1, Rd1, &redge[el1 * 16], &gse[el1 * 32], &gde[el1 * 32], lane);
        __syncthreads();
        for (int i = tid; i < 1024; i += NT_CG) {
            int n = n0 + (i >> 5), d = i & 31;
            float acc = 0.f;
            if (n <= 254) acc = gse[(n - eA) * 32 + d];
            if (n >= 1)  acc -= gde[(n - 1 - eA) * 32 + d];
            float rr = r_s[i + 32];
            float ww = fmaf(LAM_, acc, rr);
            w_s[i] = ww;
            lg = fmaf(rr, rr, lg);
            ld = fmaf(rr, ww, ld);
        }
    };
    // warp-reduce dots into wred; sync (also publishes w_s); export partials
    auto reduce_export = [&](float lg, float ld, int buf) {
#pragma unroll
        for (int o = 16; o; o >>= 1) {
            lg += __shfl_xor_sync(0xffffffffu, lg, o);
            ld += __shfl_xor_sync(0xffffffffu, ld, o);
        }
        if (lane == 0) { wred[w][0] = lg; wred[w][1] = ld; }
        __syncthreads();
        if (tid < 8) {
            float sg = 0.f, sd = 0.f;
#pragma unroll
            for (int k2 = 0; k2 < 17; k2++) { sg += wred[k2][0]; sd += wred[k2][1]; }
            st_cluster(mapa_rank(smem_u32(&part_in[buf][j][0]), (uint32_t)tid), sg);
            st_cluster(mapa_rank(smem_u32(&part_in[buf][j][1]), (uint32_t)tid), sd);
        }
    };
    auto whalo_send = [&](int buf) {
        if (tid >= 64 && tid < 96) {
            if (j > 0) st_cluster(mapa_rank(smem_u32(&wb[buf][1][tid - 64]), j - 1), w_s[tid - 64]);
        } else if (tid >= 96 && tid < 128) {
            if (j < 7) st_cluster(mapa_rank(smem_u32(&wb[buf][0][tid - 96]), j + 1), w_s[31 * 32 + tid - 96]);
        }
    };

    // ---- prolog ----
    const float* c0g = out + C0_OFF + b * (M_ * D_);
    for (int i = tid; i < 34 * 32; i += NT_CG) {
        int node = n0 - 1 + (i >> 5);
        r_s[i] = (node >= 0 && node < M_) ? c0g[node * 32 + (i & 31)] : 0.f;
    }
    __syncthreads();
    for (int i = tid; i < 1024; i += NT_CG) x_s[i] = r_s[i + 32];
    __syncthreads();

    { float z0 = 0, z1 = 0; apply_fused(z0, z1); }   // w = A c0
    __syncthreads();
    for (int i = tid; i < 1024; i += NT_CG) r_s[i + 32] = x_s[i] - w_s[i];
    __syncthreads();

    // r0 halo exchange
    if (tid < 32) {
        if (j > 0) st_cluster(mapa_rank(smem_u32(&rin[1][tid]), j - 1), r_s[32 + tid]);
    } else if (tid < 64) {
        if (j < 7) st_cluster(mapa_rank(smem_u32(&rin[0][tid - 32]), j + 1), r_s[32 * 32 + tid - 32]);
    }
    cluster_arrive_(); cluster_wait_();
    if (tid < 32) {
        if (j > 0) r_s[tid] = rin[0][tid];
    } else if (tid < 64) {
        if (j < 7) r_s[33 * 32 + (tid - 32)] = rin[1][tid - 32];
    }
    __syncthreads();

    float lg = 0.f, ld = 0.f;
    apply_fused(lg, ld);            // w = A r0 + dots
    reduce_export(lg, ld, 0);
    whalo_send(0);
    cluster_arrive_(); cluster_wait_();

    float gam = 0.f, del = 0.f;
#pragma unroll
    for (int k2 = 0; k2 < 8; k2++) { gam += part_in[0][k2][0]; del += part_in[0][k2][1]; }
    float alpha = gam / (del + 1e-12f);
    float gam_prev = gam, alpha_prev = alpha;
    float alphap = alpha;   // deferred-x multiplier

    // halo init: s_h = w_h; r_h -= alpha*s_h
    if (tid < 32) {
        if (j > 0) {
            float sv = wb[0][0][tid];
            sh_[0][tid] = sv;
            r_s[tid] = fmaf(-alpha, sv, r_s[tid]);
        }
    } else if (tid < 64) {
        if (j < 7) {
            int d2 = tid - 32;
            float sv = wb[0][1][d2];
            sh_[1][d2] = sv;
            r_s[33 * 32 + d2] = fmaf(-alpha, sv, r_s[33 * 32 + d2]);
        }
    }
    // own (beta=0): p=r, s=w, r -= alpha s   (x deferred)
    for (int i = tid; i < 1024; i += NT_CG) {
        float rr = r_s[i + 32], ww = w_s[i];
        p_s[i] = rr; s_s[i] = ww;
        r_s[i + 32] = fmaf(-alpha, ww, rr);
    }
    __syncthreads();

    // ---- main loop: ONE cluster sync per iteration ----
    for (int it = 1; it < CG_ITERS_; it++) {
        float g0 = 0.f, d0 = 0.f;
        apply_fused(g0, d0);
        const int buf = it & 1;
        reduce_export(g0, d0, buf);
        if (it < CG_ITERS_ - 1) whalo_send(buf);
        cluster_arrive_();
        // deferred x += alpha_prev * p (overlaps barrier skew)
        for (int i = tid; i < 1024; i += NT_CG)
            x_s[i] = fmaf(alphap, p_s[i], x_s[i]);
        cluster_wait_();

        gam = 0.f; del = 0.f;
#pragma unroll
        for (int k2 = 0; k2 < 8; k2++) { gam += part_in[buf][k2][0]; del += part_in[buf][k2][1]; }
        float beta = gam / (gam_prev + 1e-12f);
        alpha = gam / (del - beta * gam / alpha_prev + 1e-12f);
        gam_prev = gam; alpha_prev = alpha;

        if (it == CG_ITERS_ - 1) {
            float* og = out + C_OFF + b * (M_ * D_) + n0 * 32;
            for (int i = tid; i < 1024; i += NT_CG)
                og[i] = fmaf(alpha, fmaf(beta, p_s[i], r_s[i + 32]), x_s[i]);
            return;
        }
        alphap = alpha;

        // halos: s_h = w_h + beta*s_h; r_h -= alpha*s_h
        if (tid < 32) {
            if (j > 0) {
                float sv = fmaf(beta, sh_[0][tid], wb[buf][0][tid]);
                sh_[0][tid] = sv;
                r_s[tid] = fmaf(-alpha, sv, r_s[tid]);
            }
        } else if (tid < 64) {
            if (j < 7) {
                int d2 = tid - 32;
                float sv = fmaf(beta, sh_[1][d2], wb[buf][1][d2]);
                sh_[1][d2] = sv;
                r_s[33 * 32 + d2] = fmaf(-alpha, sv, r_s[33 * 32 + d2]);
            }
        }
        // own: p = r + beta p; s = w + beta s; r -= alpha s   (x deferred)
        for (int i = tid; i < 1024; i += NT_CG) {
            float rr = r_s[i + 32], ww = w_s[i];
            float pp = fmaf(beta, p_s[i], rr);
            float ss = fmaf(beta, s_s[i], ww);
            r_s[i + 32] = fmaf(-alpha, ss, rr);
            p_s[i] = pp; s_s[i] = ss;
        }
        __syncthreads();
    }
}

// ---------------- kernel 4: query eval (4 thr/q, prefetch all 3 phi rows) ----------------
__global__ void __launch_bounds__(256) query_kernel(
    const float* __restrict__ phi_q, const float* __restrict__ out_c,
    float* __restrict__ out)
{
    __shared__ float4 c_s[512];   // [mm(8)][b(8)][d4(8)]
    int q0 = blockIdx.x * 64;
    int mbase = (int)floorf((q0 + 0.5f) * 0.015625f) - 2;
    if (mbase < 0) mbase = 0;
    if (mbase > M_ - 8) mbase = M_ - 8;

    const float4* cg4 = (const float4*)out_c;
    for (int i = threadIdx.x; i < 512; i += 256) {
        int mm = i >> 6, rem = i & 63;
        int bb2 = rem >> 3, d4 = rem & 7;
        c_s[i] = cg4[((size_t)bb2 * M_ + (mbase + mm)) * 8 + d4];
    }
    __syncthreads();

    int ql = threadIdx.x >> 2;             // 0..63
    int dh = (threadIdx.x >> 1) & 1;       // d half
    int bh = threadIdx.x & 1;              // batch half
    int q = q0 + ql;
    float v = (q + 0.5f) * 0.015625f;
    int mlo = (int)floorf(v) - 1;

    // prefetch all 3 candidate phi rows (clamped addr, masked weight) — MLP=12
    float wr[3];
    float4 p4[3][4];
    int mc[3];
#pragma unroll
    for (int c = 0; c < 3; c++) {
        int m = mlo + c;
        int mcl = m < 0 ? 0 : (m > M_ - 1 ? M_ - 1 : m);
        mc[c] = mcl;
        const float4* ph = (const float4*)(phi_q + ((size_t)mcl * Q_ + q) * 32) + dh * 4;
        p4[c][0] = __ldg(ph + 0);
        p4[c][1] = __ldg(ph + 1);
        p4[c][2] = __ldg(ph + 2);
        p4[c][3] = __ldg(ph + 3);
        float t = (v - (m + 0.5f)) * (1.0f / 1.5f);
        float w_ = 1.0f - fabsf(t);
        wr[c] = (m >= 0 && m <= M_ - 1) ? fmaxf(w_, 0.f) : 0.f;
    }
    float wsum = wr[0] + wr[1] + wr[2];

    float sacc[4] = {0.f, 0.f, 0.f, 0.f};
#pragma unroll
    for (int c = 0; c < 3; c++) {
        int ms = mc[c] - mbase;
#pragma unroll
        for (int bb2 = 0; bb2 < 4; bb2++) {
            const float4* cc = &c_s[(ms << 6) + ((bh * 4 + bb2) << 3) + dh * 4];
            float dot = 0.f;
#pragma unroll
            for (int i = 0; i < 4; i++) {
                float4 c4 = cc[i];
                float4 pp = p4[c][i];
                dot = fmaf(pp.x, c4.x, dot);
                dot = fmaf(pp.y, c4.y, dot);
                dot = fmaf(pp.z, c4.z, dot);
                dot = fmaf(pp.w, c4.w, dot);
            }
            sacc[bb2] = fmaf(wr[c], dot, sacc[bb2]);
        }
    }
#pragma unroll
    for (int bb2 = 0; bb2 < 4; bb2++)
        sacc[bb2] += __shfl_xor_sync(0xffffffffu, sacc[bb2], 2);
    if (dh == 0) {
        float inv = 1.0f / fmaxf(wsum, 1e-8f);
#pragma unroll
        for (int bb2 = 0; bb2 < 4; bb2++)
            out[(size_t)(bh * 4 + bb2) * Q_ + q] = sacc[bb2] * inv;
    }
}

// ---------------- launch ----------------
extern "C" void kernel_launch(void* const* d_in, const int* in_sizes, int n_in,
                              void* d_out, int out_size) {
    const float* xs      = (const float*)d_in[0];
    const float* us      = (const float*)d_in[1];
    const float* phi_q   = (const float*)d_in[2];
    const float* centers = (const float*)d_in[4];
    const float* R_src   = (const float*)d_in[5];
    const float* R_dst   = (const float*)d_in[6];
    const float* W1      = (const float*)d_in[7];
    const float* b1      = (const float*)d_in[8];
    const float* W2      = (const float*)d_in[9];
    const float* b2      = (const float*)d_in[10];
    const float* W3      = (const float*)d_in[11];
    const float* b3      = (const float*)d_in[12];
    const float* Wg1     = (const float*)d_in[13];
    const float* bg1     = (const float*)d_in[14];
    const float* Wg2     = (const float*)d_in[15];
    const float* bg2     = (const float*)d_in[16];
    const int*   idx     = (const int*)d_in[17];
    float* out = (float*)d_out;

    g_kernel<<<B_, 1024>>>(xs, us, Wg1, bg1, Wg2, bg2);
    encode_kernel<<<B_ * M_ / 4, 256>>>(xs, us, centers, W1, b1, W2, b2, W3, b3, idx, out);
    cg_kernel<<<B_ * 8, NT_CG>>>(R_src, R_dst, out);
    query_kernel<<<Q_ / 64, 256>>>(phi_q, out + C_OFF, out);
}

// round 10
// speedup vs baseline: 1.3954x; 1.0015x over previous
#include <cuda_runtime.h>
#include <cuda_bf16.h>
#include <stdint.h>
#include <math.h>

#define B_ 8
#define N_ 2048
#define M_ 256
#define Q_ 16384
#define D_ 32
#define K_ 16
#define H_ 64
#define LAM_ 5.0f
#define CG_ITERS_ 20
#define RADIUS_ 0.005859375f   // 1.5/256

// out layout: s_pred [B,Q] | c0 [B,M,D] | c [B,M,D]
#define C0_OFF 131072
#define C_OFF  196608

__device__ float g_gw[B_][D_];

// ---------------- helpers ----------------
__device__ __forceinline__ uint32_t smem_u32(const void* p) {
    return (uint32_t)__cvta_generic_to_shared(p);
}
__device__ __forceinline__ uint32_t mapa_rank(uint32_t addr, uint32_t rank) {
    uint32_t r;
    asm("mapa.shared::cluster.u32 %0, %1, %2;" : "=r"(r) : "r"(addr), "r"(rank));
    return r;
}
__device__ __forceinline__ void st_cluster(uint32_t addr, float v) {
    asm volatile("st.shared::cluster.f32 [%0], %1;" :: "r"(addr), "f"(v));
}
__device__ __forceinline__ void cluster_arrive_() {
    asm volatile("barrier.cluster.arrive.aligned;" ::: "memory");
}
__device__ __forceinline__ void cluster_wait_() {
    asm volatile("barrier.cluster.wait.aligned;" ::: "memory");
}

// ---------------- kernel 1: global gate ----------------
__global__ void __launch_bounds__(1024) g_kernel(
    const float* __restrict__ xs, const float* __restrict__ us,
    const float* __restrict__ Wg1, const float* __restrict__ bg1,
    const float* __restrict__ Wg2, const float* __restrict__ bg2)
{
    int b = blockIdx.x, t = threadIdx.x;
    int h = t & 63, grp = t >> 6;
    float w0 = Wg1[h], w1 = Wg1[H_ + h], bb = bg1[h];
    float acc = 0.f;
    const float* xb = xs + b * N_;
    const float* ub = us + b * N_;
    int nbeg = grp * 128, nend = nbeg + 128;
#pragma unroll 4
    for (int n = nbeg; n < nend; n++)
        acc += fmaxf(fmaf(xb[n], w0, fmaf(ub[n], w1, bb)), 0.f);
    __shared__ float red[16][H_];
    __shared__ float gh[H_];
    red[grp][h] = acc;
    __syncthreads();
    if (t < H_) {
        float s = 0.f;
#pragma unroll
        for (int g = 0; g < 16; g++) s += red[g][t];
        gh[t] = s * (1.0f / (float)N_);
    }
    __syncthreads();
    if (t < D_) {
        float v = bg2[t];
#pragma unroll 8
        for (int hh = 0; hh < H_; hh++) v = fmaf(gh[hh], Wg2[hh * D_ + t], v);
        g_gw[b][t] = v;
    }
}

// ---------------- kernel 2: encode ----------------
__global__ void __launch_bounds__(256) encode_kernel(
    const float* __restrict__ xs, const float* __restrict__ us,
    const float* __restrict__ centers,
    const float* __restrict__ W1, const float* __restrict__ b1,
    const float* __restrict__ W2, const float* __restrict__ b2,
    const float* __restrict__ W3, const float* __restrict__ b3,
    const int* __restrict__ idx, float* __restrict__ out)
{
    __shared__ float W2s[H_ * H_];
    __shared__ __align__(16) float h1T[4][H_ * K_];
    __shared__ float rel_s[4][K_], u_s[4][K_];
    __shared__ float hb[4][H_];

    int u = threadIdx.x >> 6;
    int lt = threadIdx.x & 63;
    int bm = blockIdx.x * 4 + u;
    int b = bm >> 8, m = bm & 255;

    {
        const float4* src = (const float4*)W2;
        float4* dst = (float4*)W2s;
#pragma unroll
        for (int i = 0; i < 4; i++) dst[threadIdx.x + i * 256] = src[threadIdx.x + i * 256];
    }
    if (lt < K_) {
        int sj = idx[m * K_ + lt];
        rel_s[u][lt] = (xs[b * N_ + sj] - centers[m]) / RADIUS_;
        u_s[u][lt] = us[b * N_ + sj];
    }
    __syncthreads();

    {
        float w10 = W1[lt], w11 = W1[H_ + lt], bb1 = b1[lt];
#pragma unroll
        for (int k = 0; k < K_; k++)
            h1T[u][lt * K_ + k] = fmaxf(fmaf(rel_s[u][k], w10, fmaf(u_s[u][k], w11, bb1)), 0.f);
    }
    __syncthreads();

    {
        float acc[K_];
        float bb2 = b2[lt];
#pragma unroll
        for (int k = 0; k < K_; k++) acc[k] = bb2;
        for (int jj = 0; jj < H_; jj++) {
            float wv = W2s[jj * H_ + lt];
            const float4* hp = (const float4*)(h1T[u] + jj * K_);
#pragma unroll
            for (int kk = 0; kk < 4; kk++) {
                float4 h4 = hp[kk];
                acc[kk * 4 + 0] = fmaf(h4.x, wv, acc[kk * 4 + 0]);
                acc[kk * 4 + 1] = fmaf(h4.y, wv, acc[kk * 4 + 1]);
                acc[kk * 4 + 2] = fmaf(h4.z, wv, acc[kk * 4 + 2]);
                acc[kk * 4 + 3] = fmaf(h4.w, wv, acc[kk * 4 + 3]);
            }
        }
        float accm = 0.f;
#pragma unroll
        for (int k = 0; k < K_; k++) accm += fmaxf(acc[k], 0.f);
        hb[u][lt] = accm * (1.0f / (float)K_);
    }
    __syncthreads();

    if (lt < D_) {
        float v = b3[lt];
#pragma unroll 8
        for (int h = 0; h < H_; h++) v = fmaf(hb[u][h], W3[h * D_ + lt], v);
        out[C0_OFF + bm * D_ + lt] = v + g_gw[b][lt];
    }
}

// ---------------- kernel 3: sheaf CG (pipelined, register R, fused dots) ----------------
#define NT_CG 544   // 17 warps

__device__ __forceinline__ void edge_r_fn(const float (&Rs)[16], const float (&Rd)[16],
    const float* __restrict__ r_s, int rowA, float* __restrict__ re, int lane, int riMap)
{
    float a = r_s[rowA * 32 + lane];
    float c = r_s[rowA * 32 + 32 + lane];
    float v[16];
#pragma unroll
    for (int ri = 0; ri < 16; ri++) { v[ri] = Rs[ri] * a; v[ri] = fmaf(-Rd[ri], c, v[ri]); }
    {
        const bool bb = (lane & 16) != 0;
#pragma unroll
        for (int t = 0; t < 8; t++) {
            float snd = bb ? v[t] : v[t + 8];
            float kp  = bb ? v[t + 8] : v[t];
            v[t] = kp + __shfl_xor_sync(0xffffffffu, snd, 16);
        }
    }
    {
        const bool bb = (lane & 8) != 0;
#pragma unroll
        for (int t = 0; t < 4; t++) {
            float snd = bb ? v[t] : v[t + 4];
            float kp  = bb ? v[t + 4] : v[t];
            v[t] = kp + __shfl_xor_sync(0xffffffffu, snd, 8);
        }
    }
    {
        const bool bb = (lane & 4) != 0;
#pragma unroll
        for (int t = 0; t < 2; t++) {
            float snd = bb ? v[t] : v[t + 2];
            float kp  = bb ? v[t + 2] : v[t];
            v[t] = kp + __shfl_xor_sync(0xffffffffu, snd, 4);
        }
    }
    {
        const bool bb = (lane & 2) != 0;
        float snd = bb ? v[0] : v[1];
        float kp  = bb ? v[1] : v[0];
        v[0] = kp + __shfl_xor_sync(0xffffffffu, snd, 2);
    }
    v[0] += __shfl_xor_sync(0xffffffffu, v[0], 1);
    if ((lane & 1) == 0) re[riMap] = v[0];
}

__device__ __forceinline__ void edge_g_fn(const float (&Rs)[16], const float (&Rd)[16],
    const float* __restrict__ re, float* __restrict__ gs_o, float* __restrict__ gd_o, int lane)
{
    float gs = 0.f, gd = 0.f;
#pragma unroll
    for (int ri = 0; ri < 16; ri++) {
        float rv = re[ri];
        gs = fmaf(Rs[ri], rv, gs);
        gd = fmaf(Rd[ri], rv, gd);
    }
    gs_o[lane] = gs;
    gd_o[lane] = gd;
}

__global__ void __cluster_dims__(8, 1, 1) __launch_bounds__(NT_CG, 1) cg_kernel(
    const float* __restrict__ Rsrc, const float* __restrict__ Rdst,
    float* __restrict__ out)
{
    __shared__ float r_s[34 * 32];          // rows 0/33 = halos
    __shared__ float w_s[1024];
    __shared__ float p_s[1024];
    __shared__ float s_s[1024];
    __shared__ float x_s[1024];
    __shared__ float sh_[2][32];
    __shared__ float redge[33 * 16];
    __shared__ float gse[33 * 32], gde[33 * 32];
    __shared__ float part_in[2][8][2];
    __shared__ float rin[2][32];
    __shared__ float wb[2][2][32];
    __shared__ float wred[17][2];

    const int b = blockIdx.x >> 3, j = blockIdx.x & 7;
    const int tid = threadIdx.x, w = tid >> 5, lane = tid & 31;
    const int n0 = j * 32;
    const int eA = j ? (n0 - 1) : 0;
    const int nE = (j == 0 || j == 7) ? 32 : 33;
    const int riMap = ((lane >> 4) & 1) * 8 + ((lane >> 3) & 1) * 4 +
                      ((lane >> 2) & 1) * 2 + ((lane >> 1) & 1);

    const int el0 = 2 * w, el1 = 2 * w + 1;
    const bool h0 = el0 < nE, h1 = el1 < nE;
    const int row0 = eA + el0 - n0 + 1;
    const int row1 = row0 + 1;

    float Rs0[16], Rd0[16], Rs1[16], Rd1[16];
    if (h0) {
        const float* a = Rsrc + (size_t)(eA + el0) * 512 + lane;
        const float* d = Rdst + (size_t)(eA + el0) * 512 + lane;
#pragma unroll
        for (int ri = 0; ri < 16; ri++) { Rs0[ri] = a[ri * 32]; Rd0[ri] = d[ri * 32]; }
    }
    if (h1) {
        const float* a = Rsrc + (size_t)(eA + el1) * 512 + lane;
        const float* d = Rdst + (size_t)(eA + el1) * 512 + lane;
#pragma unroll
        for (int ri = 0; ri < 16; ri++) { Rs1[ri] = a[ri * 32]; Rd1[ri] = d[ri * 32]; }
    }

    // apply + fused dots: w = (I + LAM L) r over own nodes; lg += r.r, ld += r.w
    auto apply_fused = [&](float& lg, float& ld) {
        if (h0) edge_r_fn(Rs0, Rd0, r_s, row0, &redge[el0 * 16], lane, riMap);
        if (h1) edge_r_fn(Rs1, Rd1, r_s, row1, &redge[el1 * 16], lane, riMap);
        __syncwarp();
        if (h0) edge_g_fn(Rs0, Rd0, &redge[el0 * 16], &gse[el0 * 32], &gde[el0 * 32], lane);
        if (h1) edge_g_fn(Rs1, Rd1, &redge[el1 * 16], &gse[el1 * 32], &gde[el1 * 32], lane);
        __syncthreads();
        for (int i = tid; i < 1024; i += NT_CG) {
            int n = n0 + (i >> 5), d = i & 31;
            float acc = 0.f;
            if (n <= 254) acc = gse[(n - eA) * 32 + d];
            if (n >= 1)  acc -= gde[(n - 1 - eA) * 32 + d];
            float rr = r_s[i + 32];
            float ww = fmaf(LAM_, acc, rr);
            w_s[i] = ww;
            lg = fmaf(rr, rr, lg);
            ld = fmaf(rr, ww, ld);
        }
    };
    // warp-reduce dots into wred; sync (also publishes w_s); export partials
    auto reduce_export = [&](float lg, float ld, int buf) {
#pragma unroll
        for (int o = 16; o; o >>= 1) {
            lg += __shfl_xor_sync(0xffffffffu, lg, o);
            ld += __shfl_xor_sync(0xffffffffu, ld, o);
        }
        if (lane == 0) { wred[w][0] = lg; wred[w][1] = ld; }
        __syncthreads();
        if (tid < 8) {
            float sg = 0.f, sd = 0.f;
#pragma unroll
            for (int k2 = 0; k2 < 17; k2++) { sg += wred[k2][0]; sd += wred[k2][1]; }
            st_cluster(mapa_rank(smem_u32(&part_in[buf][j][0]), (uint32_t)tid), sg);
            st_cluster(mapa_rank(smem_u32(&part_in[buf][j][1]), (uint32_t)tid), sd);
        }
    };
    auto whalo_send = [&](int buf) {
        if (tid >= 64 && tid < 96) {
            if (j > 0) st_cluster(mapa_rank(smem_u32(&wb[buf][1][tid - 64]), j - 1), w_s[tid - 64]);
        } else if (tid >= 96 && tid < 128) {
            if (j < 7) st_cluster(mapa_rank(smem_u32(&wb[buf][0][tid - 96]), j + 1), w_s[31 * 32 + tid - 96]);
        }
    };

    // ---- prolog ----
    const float* c0g = out + C0_OFF + b * (M_ * D_);
    for (int i = tid; i < 34 * 32; i += NT_CG) {
        int node = n0 - 1 + (i >> 5);
        r_s[i] = (node >= 0 && node < M_) ? c0g[node * 32 + (i & 31)] : 0.f;
    }
    __syncthreads();
    for (int i = tid; i < 1024; i += NT_CG) x_s[i] = r_s[i + 32];
    __syncthreads();

    { float z0 = 0, z1 = 0; apply_fused(z0, z1); }   // w = A c0
    __syncthreads();
    for (int i = tid; i < 1024; i += NT_CG) r_s[i + 32] = x_s[i] - w_s[i];
    __syncthreads();

    // r0 halo exchange
    if (tid < 32) {
        if (j > 0) st_cluster(mapa_rank(smem_u32(&rin[1][tid]), j - 1), r_s[32 + tid]);
    } else if (tid < 64) {
        if (j < 7) st_cluster(mapa_rank(smem_u32(&rin[0][tid - 32]), j + 1), r_s[32 * 32 + tid - 32]);
    }
    cluster_arrive_(); cluster_wait_();
    if (tid < 32) {
        if (j > 0) r_s[tid] = rin[0][tid];
    } else if (tid < 64) {
        if (j < 7) r_s[33 * 32 + (tid - 32)] = rin[1][tid - 32];
    }
    __syncthreads();

    float lg = 0.f, ld = 0.f;
    apply_fused(lg, ld);            // w = A r0 + dots
    reduce_export(lg, ld, 0);
    whalo_send(0);
    cluster_arrive_(); cluster_wait_();

    float gam = 0.f, del = 0.f;
#pragma unroll
    for (int k2 = 0; k2 < 8; k2++) { gam += part_in[0][k2][0]; del += part_in[0][k2][1]; }
    float alpha = gam / (del + 1e-12f);
    float gam_prev = gam, alpha_prev = alpha;
    float alphap = alpha;   // deferred-x multiplier

    // halo init: s_h = w_h; r_h -= alpha*s_h
    if (tid < 32) {
        if (j > 0) {
            float sv = wb[0][0][tid];
            sh_[0][tid] = sv;
            r_s[tid] = fmaf(-alpha, sv, r_s[tid]);
        }
    } else if (tid < 64) {
        if (j < 7) {
            int d2 = tid - 32;
            float sv = wb[0][1][d2];
            sh_[1][d2] = sv;
            r_s[33 * 32 + d2] = fmaf(-alpha, sv, r_s[33 * 32 + d2]);
        }
    }
    // own (beta=0): p=r, s=w, r -= alpha s   (x deferred)
    for (int i = tid; i < 1024; i += NT_CG) {
        float rr = r_s[i + 32], ww = w_s[i];
        p_s[i] = rr; s_s[i] = ww;
        r_s[i + 32] = fmaf(-alpha, ww, rr);
    }
    __syncthreads();

    // ---- main loop: ONE cluster sync per iteration ----
    for (int it = 1; it < CG_ITERS_; it++) {
        float g0 = 0.f, d0 = 0.f;
        apply_fused(g0, d0);
        const int buf = it & 1;
        reduce_export(g0, d0, buf);
        if (it < CG_ITERS_ - 1) whalo_send(buf);
        cluster_arrive_();
        // deferred x += alpha_prev * p (overlaps barrier skew)
        for (int i = tid; i < 1024; i += NT_CG)
            x_s[i] = fmaf(alphap, p_s[i], x_s[i]);
        cluster_wait_();

        gam = 0.f; del = 0.f;
#pragma unroll
        for (int k2 = 0; k2 < 8; k2++) { gam += part_in[buf][k2][0]; del += part_in[buf][k2][1]; }
        float beta = gam / (gam_prev + 1e-12f);
        alpha = gam / (del - beta * gam / alpha_prev + 1e-12f);
        gam_prev = gam; alpha_prev = alpha;

        if (it == CG_ITERS_ - 1) {
            float* og = out + C_OFF + b * (M_ * D_) + n0 * 32;
            for (int i = tid; i < 1024; i += NT_CG)
                og[i] = fmaf(alpha, fmaf(beta, p_s[i], r_s[i + 32]), x_s[i]);
            return;
        }
        alphap = alpha;

        // halos: s_h = w_h + beta*s_h; r_h -= alpha*s_h
        if (tid < 32) {
            if (j > 0) {
                float sv = fmaf(beta, sh_[0][tid], wb[buf][0][tid]);
                sh_[0][tid] = sv;
                r_s[tid] = fmaf(-alpha, sv, r_s[tid]);
            }
        } else if (tid < 64) {
            if (j < 7) {
                int d2 = tid - 32;
                float sv = fmaf(beta, sh_[1][d2], wb[buf][1][d2]);
                sh_[1][d2] = sv;
                r_s[33 * 32 + d2] = fmaf(-alpha, sv, r_s[33 * 32 + d2]);
            }
        }
        // own: p = r + beta p; s = w + beta s; r -= alpha s   (x deferred)
        for (int i = tid; i < 1024; i += NT_CG) {
            float rr = r_s[i + 32], ww = w_s[i];
            float pp = fmaf(beta, p_s[i], rr);
            float ss = fmaf(beta, s_s[i], ww);
            r_s[i + 32] = fmaf(-alpha, ss, rr);
            p_s[i] = pp; s_s[i] = ss;
        }
        __syncthreads();
    }
}

// ---------------- kernel 4: query eval (4 thr/q, prefetch all 3 phi rows) ----------------
__global__ void __launch_bounds__(256) query_kernel(
    const float* __restrict__ phi_q, const float* __restrict__ out_c,
    float* __restrict__ out)
{
    __shared__ float4 c_s[512];   // [mm(8)][b(8)][d4(8)]
    int q0 = blockIdx.x * 64;
    int mbase = (int)floorf((q0 + 0.5f) * 0.015625f) - 2;
    if (mbase < 0) mbase = 0;
    if (mbase > M_ - 8) mbase = M_ - 8;

    const float4* cg4 = (const float4*)out_c;
    for (int i = threadIdx.x; i < 512; i += 256) {
        int mm = i >> 6, rem = i & 63;
        int bb2 = rem >> 3, d4 = rem & 7;
        c_s[i] = cg4[((size_t)bb2 * M_ + (mbase + mm)) * 8 + d4];
    }
    __syncthreads();

    int ql = threadIdx.x >> 2;             // 0..63
    int dh = (threadIdx.x >> 1) & 1;       // d half
    int bh = threadIdx.x & 1;              // batch half
    int q = q0 + ql;
    float v = (q + 0.5f) * 0.015625f;
    int mlo = (int)floorf(v) - 1;

    // prefetch all 3 candidate phi rows (clamped addr, masked weight) — MLP=12
    float wr[3];
    float4 p4[3][4];
    int mc[3];
#pragma unroll
    for (int c = 0; c < 3; c++) {
        int m = mlo + c;
        int mcl = m < 0 ? 0 : (m > M_ - 1 ? M_ - 1 : m);
        mc[c] = mcl;
        const float4* ph = (const float4*)(phi_q + ((size_t)mcl * Q_ + q) * 32) + dh * 4;
        p4[c][0] = __ldg(ph + 0);
        p4[c][1] = __ldg(ph + 1);
        p4[c][2] = __ldg(ph + 2);
        p4[c][3] = __ldg(ph + 3);
        float t = (v - (m + 0.5f)) * (1.0f / 1.5f);
        float w_ = 1.0f - fabsf(t);
        wr[c] = (m >= 0 && m <= M_ - 1) ? fmaxf(w_, 0.f) : 0.f;
    }
    float wsum = wr[0] + wr[1] + wr[2];

    float sacc[4] = {0.f, 0.f, 0.f, 0.f};
#pragma unroll
    for (int c = 0; c < 3; c++) {
        int ms = mc[c] - mbase;
#pragma unroll
        for (int bb2 = 0; bb2 < 4; bb2++) {
            const float4* cc = &c_s[(ms << 6) + ((bh * 4 + bb2) << 3) + dh * 4];
            float dot = 0.f;
#pragma unroll
            for (int i = 0; i < 4; i++) {
                float4 c4 = cc[i];
                float4 pp = p4[c][i];
                dot = fmaf(pp.x, c4.x, dot);
                dot = fmaf(pp.y, c4.y, dot);
                dot = fmaf(pp.z, c4.z, dot);
                dot = fmaf(pp.w, c4.w, dot);
            }
            sacc[bb2] = fmaf(wr[c], dot, sacc[bb2]);
        }
    }
#pragma unroll
    for (int bb2 = 0; bb2 < 4; bb2++)
        sacc[bb2] += __shfl_xor_sync(0xffffffffu, sacc[bb2], 2);
    if (dh == 0) {
        float inv = 1.0f / fmaxf(wsum, 1e-8f);
#pragma unroll
        for (int bb2 = 0; bb2 < 4; bb2++)
            out[(size_t)(bh * 4 + bb2) * Q_ + q] = sacc[bb2] * inv;
    }
}

// ---------------- launch ----------------
extern "C" void kernel_launch(void* const* d_in, const int* in_sizes, int n_in,
                              void* d_out, int out_size) {
    const float* xs      = (const float*)d_in[0];
    const float* us      = (const float*)d_in[1];
    const float* phi_q   = (const float*)d_in[2];
    const float* centers = (const float*)d_in[4];
    const float* R_src   = (const float*)d_in[5];
    const float* R_dst   = (const float*)d_in[6];
    const float* W1      = (const float*)d_in[7];
    const float* b1      = (const float*)d_in[8];
    const float* W2      = (const float*)d_in[9];
    const float* b2      = (const float*)d_in[10];
    const float* W3      = (const float*)d_in[11];
    const float* b3      = (const float*)d_in[12];
    const float* Wg1     = (const float*)d_in[13];
    const float* bg1     = (const float*)d_in[14];
    const float* Wg2     = (const float*)d_in[15];
    const float* bg2     = (const float*)d_in[16];
    const int*   idx     = (const int*)d_in[17];
    float* out = (float*)d_out;

    g_kernel<<<B_, 1024>>>(xs, us, Wg1, bg1, Wg2, bg2);
    encode_kernel<<<B_ * M_ / 4, 256>>>(xs, us, centers, W1, b1, W2, b2, W3, b3, idx, out);
    cg_kernel<<<B_ * 8, NT_CG>>>(R_src, R_dst, out);
    query_kernel<<<Q_ / 64, 256>>>(phi_q, out + C_OFF, out);
}